// round 9
// baseline (speedup 1.0000x reference)
#include <cuda_runtime.h>
#include <cuda_bf16.h>
#include <cstdint>
#include <math.h>

typedef __nv_bfloat16 bf16;
#define HEADS 16
#define DHEAD 64
#define SEQ   2048

// ---- scratch ----
constexpr size_t OXS = 0;
constexpr size_t OYS = OXS + 8388608;
constexpr size_t OWQ = OYS + 6291456;
constexpr size_t OWK = OWQ + 1048576;
constexpr size_t OWV = OWK + 786432;
constexpr size_t OWO = OWV + 786432;
constexpr size_t OQ  = OWO + 1048576;
constexpr size_t OK_ = OQ  + 8388608;
constexpr size_t OV  = OK_ + 8388608;
constexpr size_t OVT = OV  + 8388608;
constexpr size_t OAT = OVT + 8388608;
constexpr size_t TOTE = OAT + 8388608;
__device__ bf16 g_h[TOTE];
__device__ bf16 g_l[TOTE];

// ---- helpers ----
__device__ __forceinline__ uint32_t smem_u32(const void* p) {
    uint32_t a;
    asm("{ .reg .u64 t; cvta.to.shared.u64 t, %1; cvt.u32.u64 %0, t; }" : "=r"(a) : "l"(p));
    return a;
}
#define CP16(dst, src) asm volatile("cp.async.cg.shared.global [%0], [%1], 16;" :: "r"(dst), "l"(src))
#define CP_COMMIT()    asm volatile("cp.async.commit_group;" ::: "memory")
#define CP_WAIT0()     asm volatile("cp.async.wait_group 0;" ::: "memory")
#define CP_WAIT1()     asm volatile("cp.async.wait_group 1;" ::: "memory")

__device__ __forceinline__ void ldm4(uint32_t* r, uint32_t a) {
    asm volatile("ldmatrix.sync.aligned.m8n8.x4.shared.b16 {%0,%1,%2,%3}, [%4];"
        : "=r"(r[0]), "=r"(r[1]), "=r"(r[2]), "=r"(r[3]) : "r"(a));
}
__device__ __forceinline__ void mma16816(float* d, const uint32_t* a, const uint32_t* b) {
    asm volatile("mma.sync.aligned.m16n8k16.row.col.f32.bf16.bf16.f32 "
        "{%0,%1,%2,%3}, {%4,%5,%6,%7}, {%8,%9}, {%0,%1,%2,%3};"
        : "+f"(d[0]), "+f"(d[1]), "+f"(d[2]), "+f"(d[3])
        : "r"(a[0]), "r"(a[1]), "r"(a[2]), "r"(a[3]), "r"(b[0]), "r"(b[1]));
}
__device__ __forceinline__ float ex2(float x) {
    float r;
    asm("ex2.approx.f32 %0, %1;" : "=f"(r) : "f"(x));
    return r;
}
__device__ __forceinline__ void split2(float a, float b, uint32_t& hi, uint32_t& lo) {
    bf16 ha = __float2bfloat16_rn(a), hb = __float2bfloat16_rn(b);
    __nv_bfloat162 H, L;
    H.x = ha; H.y = hb;
    L.x = __float2bfloat16_rn(a - __bfloat162float(ha));
    L.y = __float2bfloat16_rn(b - __bfloat162float(hb));
    hi = *reinterpret_cast<uint32_t*>(&H);
    lo = *reinterpret_cast<uint32_t*>(&L);
}

// ---- elementwise split ----
__global__ __launch_bounds__(256) void split_kernel(
    const float* __restrict__ src, bf16* __restrict__ h, bf16* __restrict__ l, int n4)
{
    int i = blockIdx.x * 256 + threadIdx.x;
    if (i >= n4) return;
    float4 v = reinterpret_cast<const float4*>(src)[i];
    uint32_t h0, l0, h1, l1;
    split2(v.x, v.y, h0, l0);
    split2(v.z, v.w, h1, l1);
    reinterpret_cast<uint2*>(h)[i] = make_uint2(h0, h1);
    reinterpret_cast<uint2*>(l)[i] = make_uint2(l0, l1);
}

// ---- weight transpose+split ----
__global__ void wtsplit_kernel(const float* __restrict__ W,
                               bf16* __restrict__ th, bf16* __restrict__ tl, int K, int N)
{
    __shared__ float t[32][33];
    int n0 = blockIdx.x * 32, k0 = blockIdx.y * 32;
    int tx = threadIdx.x, ty = threadIdx.y;
    for (int i = ty; i < 32; i += 8) t[i][tx] = W[(size_t)(k0 + i) * N + n0 + tx];
    __syncthreads();
    for (int i = ty; i < 32; i += 8) {
        float v = t[tx][i];
        bf16 h = __float2bfloat16_rn(v);
        size_t o = (size_t)(n0 + i) * K + k0 + tx;
        th[o] = h;
        tl[o] = __float2bfloat16_rn(v - __bfloat162float(h));
    }
}

// ---- V transpose ----
__global__ void vtrans_kernel(const bf16* __restrict__ vh, const bf16* __restrict__ vl,
                              bf16* __restrict__ oh, bf16* __restrict__ ol)
{
    __shared__ bf16 th[32][33], tl[32][33];
    int bh = blockIdx.z;
    size_t ib = (size_t)bh * SEQ * DHEAD, ob = (size_t)bh * DHEAD * SEQ;
    int s0 = blockIdx.x * 32, d0 = blockIdx.y * 32;
    int tx = threadIdx.x, ty = threadIdx.y;
    for (int i = ty; i < 32; i += 8) {
        size_t o = ib + (size_t)(s0 + i) * DHEAD + d0 + tx;
        th[i][tx] = vh[o]; tl[i][tx] = vl[o];
    }
    __syncthreads();
    for (int i = ty; i < 32; i += 8) {
        size_t o = ob + (size_t)(d0 + i) * SEQ + s0 + tx;
        oh[o] = th[tx][i]; ol[o] = tl[tx][i];
    }
}

// ============================================================================
// GEMM: K-chunk 32, swizzled 64B rows, 3-stage pipeline, B loads via ldm4 pairs.
// ============================================================================
#define GBUF 32768
#define GSM  98304

__global__ __launch_bounds__(256, 2) void gemm_mma_kernel(
    const bf16* __restrict__ Ah, const bf16* __restrict__ Al,
    const bf16* __restrict__ Bh, const bf16* __restrict__ Bl,
    const float* __restrict__ bias, bf16* __restrict__ oh, bf16* __restrict__ ol,
    float* __restrict__ of, int K, float scale, int mode)
{
    extern __shared__ __align__(16) char sm[];
    uint32_t sb = smem_u32(sm);
    const int tid = threadIdx.x, warp = tid >> 5, lane = tid & 31;
    const int wm = warp & 1, wn = warp >> 1;
    const int m0 = blockIdx.y * 128, n0 = blockIdx.x * 128;

    auto prefetch = [&](int t, int buf) {
        uint32_t base = sb + buf * GBUF;
        int k0 = t * 32;
        #pragma unroll
        for (int i = 0; i < 2; i++) {
            int g2 = tid + i * 256;
            int row = g2 >> 2, c8 = g2 & 3;
            uint32_t doff = row * 64 + (uint32_t)((c8 ^ ((row >> 1) & 3)) << 4);
            size_t sa  = (size_t)(m0 + row) * K + k0 + c8 * 8;
            size_t sbv = (size_t)(n0 + row) * K + k0 + c8 * 8;
            CP16(base + doff,         Ah + sa);
            CP16(base + 8192 + doff,  Al + sa);
            CP16(base + 16384 + doff, Bh + sbv);
            CP16(base + 24576 + doff, Bl + sbv);
        }
    };

    float acc[4][4][4];
    #pragma unroll
    for (int a = 0; a < 4; a++)
        #pragma unroll
        for (int b = 0; b < 4; b++)
            #pragma unroll
            for (int c = 0; c < 4; c++) acc[a][b][c] = 0.f;

    const int nT = K >> 5;
    prefetch(0, 0); CP_COMMIT();
    prefetch(1, 1); CP_COMMIT();

    const int arow0 = wm * 64 + (lane & 7) + ((lane >> 3) & 1) * 8;
    const int agk   = (lane >> 4) & 1;
    const int brow4 = ((lane >> 4) & 1) * 8 + (lane & 7);   // x4 pair row
    const int bkh   = (lane >> 3) & 1;                      // k-half

    int buf = 0;
    for (int t = 0; t < nT; t++) {
        if (t < nT - 1) CP_WAIT1(); else CP_WAIT0();
        __syncthreads();
        if (t + 2 < nT) { prefetch(t + 2, (buf + 2) % 3); CP_COMMIT(); }
        uint32_t base = sb + buf * GBUF;
        #pragma unroll
        for (int ks = 0; ks < 2; ks++) {
            uint32_t ah[4][4], al[4][4];
            const int gA = 2 * ks + agk;
            #pragma unroll
            for (int mi = 0; mi < 4; mi++) {
                const int rl = arow0 + mi * 16;
                uint32_t ad = base + rl * 64 + (uint32_t)((gA ^ ((rl >> 1) & 3)) << 4);
                ldm4(ah[mi], ad);
                ldm4(al[mi], ad + 8192);
            }
            const int gB = 2 * ks + bkh;
            #pragma unroll
            for (int np = 0; np < 2; np++) {
                const int rl = wn * 32 + np * 16 + brow4;
                uint32_t bd = base + 16384 + rl * 64 + (uint32_t)((gB ^ ((rl >> 1) & 3)) << 4);
                uint32_t bh4[4], bl4[4];
                ldm4(bh4, bd);
                ldm4(bl4, bd + 8192);
                #pragma unroll
                for (int mi = 0; mi < 4; mi++) {
                    mma16816(acc[mi][2*np],   ah[mi], bh4);
                    mma16816(acc[mi][2*np],   al[mi], bh4);
                    mma16816(acc[mi][2*np],   ah[mi], bl4);
                    mma16816(acc[mi][2*np+1], ah[mi], bh4 + 2);
                    mma16816(acc[mi][2*np+1], al[mi], bh4 + 2);
                    mma16816(acc[mi][2*np+1], ah[mi], bl4 + 2);
                }
            }
        }
        buf = (buf + 1) % 3;
    }

    const int g = lane >> 2, c2 = (lane & 3) * 2;
    #pragma unroll
    for (int mi = 0; mi < 4; mi++) {
        const int r0 = m0 + wm * 64 + mi * 16 + g;
        #pragma unroll
        for (int ni = 0; ni < 4; ni++) {
            const int cc = n0 + wn * 32 + ni * 8 + c2;
            const float b0 = bias[cc], b1 = bias[cc + 1];
            if (mode == 0) {
                #pragma unroll
                for (int rr = 0; rr < 2; rr++) {
                    const int r = r0 + rr * 8;
                    float f0 = (acc[mi][ni][rr * 2 + 0] + b0) * scale;
                    float f1 = (acc[mi][ni][rr * 2 + 1] + b1) * scale;
                    uint32_t hi, lo;
                    split2(f0, f1, hi, lo);
                    const int bb = r >> 11, s = r & 2047, hh = cc >> 6, d = cc & 63;
                    size_t off = (((size_t)bb * HEADS + hh) * SEQ + s) * DHEAD + d;
                    *reinterpret_cast<uint32_t*>(&oh[off]) = hi;
                    *reinterpret_cast<uint32_t*>(&ol[off]) = lo;
                }
            } else {
                *reinterpret_cast<float2*>(&of[(size_t)r0 * 1024 + cc]) =
                    make_float2(acc[mi][ni][0] + b0, acc[mi][ni][1] + b1);
                *reinterpret_cast<float2*>(&of[(size_t)(r0 + 8) * 1024 + cc]) =
                    make_float2(acc[mi][ni][2] + b0, acc[mi][ni][3] + b1);
            }
        }
    }
}

// ============================================================================
// Flash attention: Q frags hoisted to regs; B loads via ldm4 pairs; 1 sync/iter.
// ============================================================================
#define SKB 144
#define AQH 0
#define AQL 18432
#define AKV 36864
#define ABUF 36864
#define ASMT 110592

__global__ __launch_bounds__(256, 2) void attn_mma_kernel(
    const bf16* __restrict__ qh, const bf16* __restrict__ ql,
    const bf16* __restrict__ kh, const bf16* __restrict__ kl,
    const bf16* __restrict__ vth, const bf16* __restrict__ vtl,
    bf16* __restrict__ ath, bf16* __restrict__ atl)
{
    extern __shared__ __align__(16) char sm[];
    uint32_t sb = smem_u32(sm);
    const int tid = threadIdx.x, warp = tid >> 5, lane = tid & 31;
    const int qt = blockIdx.x, hd = blockIdx.y, bz = blockIdx.z;
    const int bhi = bz * HEADS + hd;

    const bf16* qhp = qh + ((size_t)bhi * SEQ + qt * 128) * DHEAD;
    const bf16* qlp = ql + ((size_t)bhi * SEQ + qt * 128) * DHEAD;
    const bf16* khp = kh + (size_t)bhi * SEQ * DHEAD;
    const bf16* klp = kl + (size_t)bhi * SEQ * DHEAD;
    const bf16* vhp = vth + (size_t)bhi * DHEAD * SEQ;
    const bf16* vlp = vtl + (size_t)bhi * DHEAD * SEQ;

    #pragma unroll
    for (int i = 0; i < 4; i++) {
        int gi = tid + i * 256;
        int row = gi >> 3, c8 = gi & 7;
        uint32_t doff = row * SKB + c8 * 16;
        CP16(sb + AQH + doff, qhp + (size_t)row * DHEAD + c8 * 8);
        CP16(sb + AQL + doff, qlp + (size_t)row * DHEAD + c8 * 8);
    }
    CP_COMMIT();

    auto kvpf = [&](int it, int bufb) {
        int s0 = it * 64;
        uint32_t base = sb + AKV + bufb * ABUF;
        #pragma unroll
        for (int i = 0; i < 2; i++) {
            int gi = tid + i * 256;
            int row = gi >> 3, c8 = gi & 7;
            uint32_t doff = row * SKB + c8 * 16;
            CP16(base + doff,         khp + (size_t)(s0 + row) * DHEAD + c8 * 8);
            CP16(base + 9216 + doff,  klp + (size_t)(s0 + row) * DHEAD + c8 * 8);
            CP16(base + 18432 + doff, vhp + (size_t)row * SEQ + s0 + c8 * 8);
            CP16(base + 27648 + doff, vlp + (size_t)row * SEQ + s0 + c8 * 8);
        }
    };
    kvpf(0, 0); CP_COMMIT();

    // wait for Q, then load Q fragments into registers (loop-invariant)
    const int arow = warp * 16 + (lane & 7) + ((lane >> 3) & 1) * 8;
    const int acolh = (lane >> 4) * 8;
    CP_WAIT1();
    __syncthreads();
    uint32_t qhf[4][4], qlf[4][4];
    #pragma unroll
    for (int ks = 0; ks < 4; ks++) {
        uint32_t ao = sb + arow * SKB + (ks * 16 + acolh) * 2;
        ldm4(qhf[ks], ao + AQH);
        ldm4(qlf[ks], ao + AQL);
    }

    float o[8][4];
    #pragma unroll
    for (int n = 0; n < 8; n++)
        #pragma unroll
        for (int c = 0; c < 4; c++) o[n][c] = 0.f;
    float m0r = -1e30f, m1r = -1e30f, l0 = 0.f, l1 = 0.f;

    const int brow4 = ((lane >> 4) & 1) * 8 + (lane & 7);
    const int bk8   = ((lane >> 3) & 1) * 8;

    for (int it = 0; it < 32; it++) {
        CP_WAIT0();
        __syncthreads();
        if (it + 1 < 32) { kvpf(it + 1, (it + 1) & 1); CP_COMMIT(); }
        uint32_t kbh = sb + AKV + (it & 1) * ABUF;
        uint32_t kbl = kbh + 9216, vbh = kbh + 18432, vbl = kbh + 27648;

        float s[8][4];
        #pragma unroll
        for (int n = 0; n < 8; n++)
            #pragma unroll
            for (int c = 0; c < 4; c++) s[n][c] = 0.f;
        #pragma unroll
        for (int ks = 0; ks < 4; ks++) {
            uint32_t bo = (ks * 16 + bk8) * 2;
            #pragma unroll
            for (int j = 0; j < 4; j++) {
                uint32_t ro = (j * 16 + brow4) * SKB + bo;
                uint32_t bh4[4], bl4[4];
                ldm4(bh4, kbh + ro);
                ldm4(bl4, kbl + ro);
                mma16816(s[2*j],   qhf[ks], bh4);
                mma16816(s[2*j],   qlf[ks], bh4);
                mma16816(s[2*j],   qhf[ks], bl4);
                mma16816(s[2*j+1], qhf[ks], bh4 + 2);
                mma16816(s[2*j+1], qlf[ks], bh4 + 2);
                mma16816(s[2*j+1], qhf[ks], bl4 + 2);
            }
        }

        float mx0 = -1e30f, mx1 = -1e30f;
        #pragma unroll
        for (int n = 0; n < 8; n++) {
            mx0 = fmaxf(mx0, fmaxf(s[n][0], s[n][1]));
            mx1 = fmaxf(mx1, fmaxf(s[n][2], s[n][3]));
        }
        mx0 = fmaxf(mx0, __shfl_xor_sync(0xffffffffu, mx0, 1));
        mx0 = fmaxf(mx0, __shfl_xor_sync(0xffffffffu, mx0, 2));
        mx1 = fmaxf(mx1, __shfl_xor_sync(0xffffffffu, mx1, 1));
        mx1 = fmaxf(mx1, __shfl_xor_sync(0xffffffffu, mx1, 2));
        const float mn0 = fmaxf(m0r, mx0), mn1 = fmaxf(m1r, mx1);
        const float c0 = ex2(m0r - mn0), c1 = ex2(m1r - mn1);
        float rs0 = 0.f, rs1 = 0.f;
        #pragma unroll
        for (int n = 0; n < 8; n++) {
            s[n][0] = ex2(s[n][0] - mn0); s[n][1] = ex2(s[n][1] - mn0);
            s[n][2] = ex2(s[n][2] - mn1); s[n][3] = ex2(s[n][3] - mn1);
            rs0 += s[n][0] + s[n][1];
            rs1 += s[n][2] + s[n][3];
        }
        rs0 += __shfl_xor_sync(0xffffffffu, rs0, 1);
        rs0 += __shfl_xor_sync(0xffffffffu, rs0, 2);
        rs1 += __shfl_xor_sync(0xffffffffu, rs1, 1);
        rs1 += __shfl_xor_sync(0xffffffffu, rs1, 2);
        l0 = l0 * c0 + rs0; l1 = l1 * c1 + rs1;
        m0r = mn0; m1r = mn1;
        #pragma unroll
        for (int n = 0; n < 8; n++) {
            o[n][0] *= c0; o[n][1] *= c0; o[n][2] *= c1; o[n][3] *= c1;
        }

        #pragma unroll
        for (int ks = 0; ks < 4; ks++) {
            uint32_t ph4[4], pl4[4];
            split2(s[2 * ks][0],     s[2 * ks][1],     ph4[0], pl4[0]);
            split2(s[2 * ks][2],     s[2 * ks][3],     ph4[1], pl4[1]);
            split2(s[2 * ks + 1][0], s[2 * ks + 1][1], ph4[2], pl4[2]);
            split2(s[2 * ks + 1][2], s[2 * ks + 1][3], ph4[3], pl4[3]);
            uint32_t bo = (ks * 16 + bk8) * 2;
            #pragma unroll
            for (int j = 0; j < 4; j++) {
                uint32_t ro = (j * 16 + brow4) * SKB + bo;
                uint32_t vh4[4], vl4[4];
                ldm4(vh4, vbh + ro);
                ldm4(vl4, vbl + ro);
                mma16816(o[2*j],   ph4, vh4);
                mma16816(o[2*j],   pl4, vh4);
                mma16816(o[2*j],   ph4, vl4);
                mma16816(o[2*j+1], ph4, vh4 + 2);
                mma16816(o[2*j+1], pl4, vh4 + 2);
                mma16816(o[2*j+1], ph4, vl4 + 2);
            }
        }
    }

    const float i0 = 1.f / l0, i1 = 1.f / l1;
    const int r0 = qt * 128 + warp * 16 + (lane >> 2);
    const size_t rowA = ((size_t)bz * SEQ + r0) * 1024 + hd * 64;
    const size_t rowB = rowA + (size_t)8 * 1024;
    #pragma unroll
    for (int ni = 0; ni < 8; ni++) {
        const int d0 = ni * 8 + (lane & 3) * 2;
        uint32_t hi, lo;
        split2(o[ni][0] * i0, o[ni][1] * i0, hi, lo);
        *reinterpret_cast<uint32_t*>(&ath[rowA + d0]) = hi;
        *reinterpret_cast<uint32_t*>(&atl[rowA + d0]) = lo;
        split2(o[ni][2] * i1, o[ni][3] * i1, hi, lo);
        *reinterpret_cast<uint32_t*>(&ath[rowB + d0]) = hi;
        *reinterpret_cast<uint32_t*>(&atl[rowB + d0]) = lo;
    }
}

// ---- launch ----
extern "C" void kernel_launch(void* const* d_in, const int* in_sizes, int n_in,
                              void* d_out, int out_size)
{
    const float* x  = (const float*)d_in[0];
    const float* y  = (const float*)d_in[1];
    const float* Wq = (const float*)d_in[2];
    const float* bq = (const float*)d_in[3];
    const float* Wk = (const float*)d_in[4];
    const float* bk = (const float*)d_in[5];
    const float* Wv = (const float*)d_in[6];
    const float* bv = (const float*)d_in[7];
    const float* Wo = (const float*)d_in[8];
    const float* bo = (const float*)d_in[9];
    float* out = (float*)d_out;

    bf16 *H, *L;
    cudaGetSymbolAddress((void**)&H, g_h);
    cudaGetSymbolAddress((void**)&L, g_l);

    cudaFuncSetAttribute(gemm_mma_kernel, cudaFuncAttributeMaxDynamicSharedMemorySize, GSM);
    cudaFuncSetAttribute(attn_mma_kernel, cudaFuncAttributeMaxDynamicSharedMemorySize, ASMT);

    split_kernel<<<8192, 256>>>(x, H + OXS, L + OXS, 2097152);
    split_kernel<<<6144, 256>>>(y, H + OYS, L + OYS, 1572864);
    wtsplit_kernel<<<dim3(32, 32), dim3(32, 8)>>>(Wq, H + OWQ, L + OWQ, 1024, 1024);
    wtsplit_kernel<<<dim3(32, 24), dim3(32, 8)>>>(Wk, H + OWK, L + OWK, 768, 1024);
    wtsplit_kernel<<<dim3(32, 24), dim3(32, 8)>>>(Wv, H + OWV, L + OWV, 768, 1024);
    wtsplit_kernel<<<dim3(32, 32), dim3(32, 8)>>>(Wo, H + OWO, L + OWO, 1024, 1024);

    const float qscale = 0.125f * 1.44269504088896341f;
    dim3 gg(8, 64);
    gemm_mma_kernel<<<gg, 256, GSM>>>(H + OXS, L + OXS, H + OWQ, L + OWQ, bq,
                                      H + OQ, L + OQ, nullptr, 1024, qscale, 0);
    gemm_mma_kernel<<<gg, 256, GSM>>>(H + OYS, L + OYS, H + OWK, L + OWK, bk,
                                      H + OK_, L + OK_, nullptr, 768, 1.0f, 0);
    gemm_mma_kernel<<<gg, 256, GSM>>>(H + OYS, L + OYS, H + OWV, L + OWV, bv,
                                      H + OV, L + OV, nullptr, 768, 1.0f, 0);
    vtrans_kernel<<<dim3(64, 2, 64), dim3(32, 8)>>>(H + OV, L + OV, H + OVT, L + OVT);

    attn_mma_kernel<<<dim3(16, 16, 4), 256, ASMT>>>(H + OQ, L + OQ, H + OK_, L + OK_,
                                                    H + OVT, L + OVT, H + OAT, L + OAT);

    gemm_mma_kernel<<<gg, 256, GSM>>>(H + OAT, L + OAT, H + OWO, L + OWO, bo,
                                      nullptr, nullptr, out, 1024, 1.0f, 1);
}